// round 2
// baseline (speedup 1.0000x reference)
#include <cuda_runtime.h>
#include <math.h>

#define BQ 16
#define NQ 4096
#define SQ 1024
#define KQ 32
#define CQ 64
#define HQ 128

// scratch: group indices (allocation-free per harness rules)
__device__ int g_group_idx[BQ * SQ * KQ];

// ---------------------------------------------------------------------------
// Kernel 1: farthest point sampling. One block per batch, 1024 threads.
// Each thread keeps its 4 points + dist_min in REGISTERS (no big smem).
// After block argmax, the owning thread publishes the new center.
// Matches jnp.argmax first-index tie-breaking exactly.
// ---------------------------------------------------------------------------
__global__ __launch_bounds__(1024) void fps_kernel(
    const float* __restrict__ xyz, float* __restrict__ new_xyz)
{
    const int b = blockIdx.x;
    const int t = threadIdx.x;
    __shared__ float rv[32];
    __shared__ int   ri[32];
    __shared__ float s_c[3];
    __shared__ int   s_bi;

    float px[4], py[4], pz[4], dmin[4];
    const float* xb = xyz + (size_t)b * NQ * 3;
#pragma unroll
    for (int r = 0; r < 4; r++) {
        int p = t + r * 1024;
        px[r] = xb[3 * p + 0];
        py[r] = xb[3 * p + 1];
        pz[r] = xb[3 * p + 2];
    }
    if (t == 0) {
        s_c[0] = px[0]; s_c[1] = py[0]; s_c[2] = pz[0];
        float* o = &new_xyz[(size_t)b * SQ * 3];
        o[0] = px[0]; o[1] = py[0]; o[2] = pz[0];
    }
    __syncthreads();
    float cx = s_c[0], cy = s_c[1], cz = s_c[2];
#pragma unroll
    for (int r = 0; r < 4; r++) {
        float dx = px[r] - cx, dy = py[r] - cy, dz = pz[r] - cz;
        dmin[r] = dx * dx + dy * dy + dz * dz;
    }

    for (int i = 1; i < SQ; i++) {
        // local argmax over this thread's 4 points (ascending p, strict >)
        float bv = -1.0f;
        int   bi = 0;
#pragma unroll
        for (int r = 0; r < 4; r++) {
            if (dmin[r] > bv) { bv = dmin[r]; bi = t + r * 1024; }
        }
        // warp argmax (tie -> lower index)
#pragma unroll
        for (int o = 16; o > 0; o >>= 1) {
            float ov = __shfl_down_sync(0xffffffffu, bv, o);
            int   oi = __shfl_down_sync(0xffffffffu, bi, o);
            if (ov > bv || (ov == bv && oi < bi)) { bv = ov; bi = oi; }
        }
        if ((t & 31) == 0) { rv[t >> 5] = bv; ri[t >> 5] = bi; }
        __syncthreads();
        if (t < 32) {
            bv = rv[t]; bi = ri[t];
#pragma unroll
            for (int o = 16; o > 0; o >>= 1) {
                float ov = __shfl_down_sync(0xffffffffu, bv, o);
                int   oi = __shfl_down_sync(0xffffffffu, bi, o);
                if (ov > bv || (ov == bv && oi < bi)) { bv = ov; bi = oi; }
            }
            if (t == 0) s_bi = bi;
        }
        __syncthreads();
        const int w = s_bi;
        if (t == (w & 1023)) {
            const int r = w >> 10;
            s_c[0] = px[r]; s_c[1] = py[r]; s_c[2] = pz[r];
            float* o = &new_xyz[((size_t)b * SQ + i) * 3];
            o[0] = px[r]; o[1] = py[r]; o[2] = pz[r];
        }
        __syncthreads();
        cx = s_c[0]; cy = s_c[1]; cz = s_c[2];
#pragma unroll
        for (int r = 0; r < 4; r++) {
            float dx = px[r] - cx, dy = py[r] - cy, dz = pz[r] - cz;
            float d = dx * dx + dy * dy + dz * dz;
            dmin[r] = d < dmin[r] ? d : dmin[r];
        }
    }
}

// ---------------------------------------------------------------------------
// Kernel 2: ball query. 1 thread per center; batch xyz cached in smem
// (exactly 48KB dynamic, ZERO static smem -> within default limit).
// Top-32 by lexicographic (dist_or_inf, idx) == stable argsort semantics.
// ---------------------------------------------------------------------------
__global__ __launch_bounds__(128) void ball_kernel(
    const float* __restrict__ xyz, const float* __restrict__ new_xyz)
{
    const int blk = blockIdx.x;
    const int b = blk >> 3;              // 8 blocks per batch
    const int t = threadIdx.x;
    const int s = ((blk & 7) << 7) + t;  // center index within batch

    extern __shared__ float sm[];
    float* xs = sm;
    float* ys = sm + NQ;
    float* zs = sm + 2 * NQ;
    const float* xb = xyz + (size_t)b * NQ * 3;
    for (int idx = t; idx < NQ * 3; idx += 128) {
        float v = xb[idx];
        int p = idx / 3;
        int j = idx - 3 * p;
        if (j == 0) xs[p] = v; else if (j == 1) ys[p] = v; else zs[p] = v;
    }
    __syncthreads();

    const float* cc = &new_xyz[((size_t)b * SQ + s) * 3];
    const float cx = cc[0], cy = cc[1], cz = cc[2];
    const float INF = __int_as_float(0x7f800000);

    float nd[KQ];
    int   ni[KQ];
#pragma unroll
    for (int j = 0; j < KQ; j++) { nd[j] = INF; ni[j] = 0x7fffffff; }
    float wd = INF;
    int   wi = 0x7fffffff;

    for (int p = 0; p < NQ; p++) {
        float dx = xs[p] - cx, dy = ys[p] - cy, dz = zs[p] - cz;
        float d = dx * dx + dy * dy + dz * dz;
        float key = (d <= 0.04f) ? d : INF;
        if (key < wd || (key == wd && p < wi)) {
            int j = KQ - 1;
            while (j > 0) {
                float pd = nd[j - 1];
                int   pi = ni[j - 1];
                if (pd > key || (pd == key && pi > p)) { nd[j] = pd; ni[j] = pi; j--; }
                else break;
            }
            nd[j] = key; ni[j] = p;
            wd = nd[KQ - 1]; wi = ni[KQ - 1];
        }
    }

    int* go = &g_group_idx[((size_t)b * SQ + s) * KQ];
#pragma unroll
    for (int j = 0; j < KQ; j++) go[j] = ni[j];
}

// ---------------------------------------------------------------------------
// Kernel 3: fused gather + 4-layer MLP + attention-weighted sum.
// One block per center, 128 threads = 1 output channel each.
// Activations kept K-transposed in smem (rows padded to 36 floats for
// 16B-aligned float4 broadcast reads).
// ---------------------------------------------------------------------------
__global__ __launch_bounds__(128) void mlp_kernel(
    const float* __restrict__ xyz, const float* __restrict__ feats,
    const float* __restrict__ new_xyz,
    const float* __restrict__ W1, const float* __restrict__ b1,
    const float* __restrict__ W2, const float* __restrict__ b2,
    const float* __restrict__ W3, const float* __restrict__ b3,
    const float* __restrict__ W4, const float* __restrict__ b4,
    float* __restrict__ f_out)
{
    const int bs = blockIdx.x;       // b*SQ + s
    const int b  = bs >> 10;
    const int t  = threadIdx.x;      // output channel

    __shared__ __align__(16) float xn[3 * 36];       // grouped_xyz_norm^T
    __shared__ __align__(16) float bufA[128 * 36];   // features^T / (f'-mean)^T
    __shared__ __align__(16) float bufB[128 * 36];   // h^T / g^T
    __shared__ int   gi[KQ];
    __shared__ float ctr[3];

    if (t < KQ) gi[t] = g_group_idx[(size_t)bs * KQ + t];
    if (t >= KQ && t < KQ + 3) ctr[t - KQ] = new_xyz[(size_t)bs * 3 + (t - KQ)];
    __syncthreads();

    // gather features (coalesced rows of 64 floats per neighbor)
    const float* fb = feats + (size_t)b * NQ * CQ;
    for (int e = t; e < KQ * CQ; e += 128) {
        int k = e >> 6, c = e & 63;
        bufA[c * 36 + k] = fb[(size_t)gi[k] * CQ + c];
    }
    // gather xyz and normalize
    if (t < 96) {
        int k = t & 31, j = t >> 5;
        xn[j * 36 + k] = xyz[((size_t)b * NQ + gi[k]) * 3 + j] - ctr[j];
    }
    __syncthreads();

    float acc[KQ];
#pragma unroll
    for (int k = 0; k < KQ; k++) acc[k] = 0.f;

    // ----- Layer 1: 67 -> 128, relu -----
#pragma unroll
    for (int i = 0; i < 3; i++) {
        float w = __ldg(&W1[i * HQ + t]);
        const float4* r4 = (const float4*)&xn[i * 36];
#pragma unroll
        for (int j = 0; j < 8; j++) {
            float4 v = r4[j];
            acc[4*j+0] = fmaf(v.x, w, acc[4*j+0]);
            acc[4*j+1] = fmaf(v.y, w, acc[4*j+1]);
            acc[4*j+2] = fmaf(v.z, w, acc[4*j+2]);
            acc[4*j+3] = fmaf(v.w, w, acc[4*j+3]);
        }
    }
#pragma unroll 4
    for (int i = 0; i < CQ; i++) {
        float w = __ldg(&W1[(3 + i) * HQ + t]);
        const float4* r4 = (const float4*)&bufA[i * 36];
#pragma unroll
        for (int j = 0; j < 8; j++) {
            float4 v = r4[j];
            acc[4*j+0] = fmaf(v.x, w, acc[4*j+0]);
            acc[4*j+1] = fmaf(v.y, w, acc[4*j+1]);
            acc[4*j+2] = fmaf(v.z, w, acc[4*j+2]);
            acc[4*j+3] = fmaf(v.w, w, acc[4*j+3]);
        }
    }
    {
        float bb = __ldg(&b1[t]);
#pragma unroll
        for (int k = 0; k < KQ; k++) bufB[t * 36 + k] = fmaxf(acc[k] + bb, 0.f);
    }
    __syncthreads();

    // ----- Layer 2: 128 -> 128, relu -> f_prime (kept in regs) -----
    float fp[KQ];
#pragma unroll
    for (int k = 0; k < KQ; k++) fp[k] = 0.f;
#pragma unroll 4
    for (int i = 0; i < HQ; i++) {
        float w = __ldg(&W2[i * HQ + t]);
        const float4* r4 = (const float4*)&bufB[i * 36];
#pragma unroll
        for (int j = 0; j < 8; j++) {
            float4 v = r4[j];
            fp[4*j+0] = fmaf(v.x, w, fp[4*j+0]);
            fp[4*j+1] = fmaf(v.y, w, fp[4*j+1]);
            fp[4*j+2] = fmaf(v.z, w, fp[4*j+2]);
            fp[4*j+3] = fmaf(v.w, w, fp[4*j+3]);
        }
    }
    float m = 0.f;
    {
        float bb = __ldg(&b2[t]);
#pragma unroll
        for (int k = 0; k < KQ; k++) { fp[k] = fmaxf(fp[k] + bb, 0.f); m += fp[k]; }
        m *= (1.f / (float)KQ);
    }
    // write (f_prime - mean)^T into bufA (layer-1 reads of bufA are done)
#pragma unroll
    for (int k = 0; k < KQ; k++) bufA[t * 36 + k] = fp[k] - m;
    __syncthreads();

    // ----- Layer 3: 131 -> 128, relu -----
#pragma unroll
    for (int k = 0; k < KQ; k++) acc[k] = 0.f;
#pragma unroll
    for (int i = 0; i < 3; i++) {
        float w = __ldg(&W3[i * HQ + t]);
        const float4* r4 = (const float4*)&xn[i * 36];
#pragma unroll
        for (int j = 0; j < 8; j++) {
            float4 v = r4[j];
            acc[4*j+0] = fmaf(v.x, w, acc[4*j+0]);
            acc[4*j+1] = fmaf(v.y, w, acc[4*j+1]);
            acc[4*j+2] = fmaf(v.z, w, acc[4*j+2]);
            acc[4*j+3] = fmaf(v.w, w, acc[4*j+3]);
        }
    }
#pragma unroll 4
    for (int i = 0; i < HQ; i++) {
        float w = __ldg(&W3[(3 + i) * HQ + t]);
        const float4* r4 = (const float4*)&bufA[i * 36];
#pragma unroll
        for (int j = 0; j < 8; j++) {
            float4 v = r4[j];
            acc[4*j+0] = fmaf(v.x, w, acc[4*j+0]);
            acc[4*j+1] = fmaf(v.y, w, acc[4*j+1]);
            acc[4*j+2] = fmaf(v.z, w, acc[4*j+2]);
            acc[4*j+3] = fmaf(v.w, w, acc[4*j+3]);
        }
    }
    {
        float bb = __ldg(&b3[t]);
#pragma unroll
        for (int k = 0; k < KQ; k++) bufB[t * 36 + k] = fmaxf(acc[k] + bb, 0.f);
    }
    __syncthreads();

    // ----- Layer 4: 128 -> 128, sigmoid; weighted sum -----
#pragma unroll
    for (int k = 0; k < KQ; k++) acc[k] = 0.f;
#pragma unroll 4
    for (int i = 0; i < HQ; i++) {
        float w = __ldg(&W4[i * HQ + t]);
        const float4* r4 = (const float4*)&bufB[i * 36];
#pragma unroll
        for (int j = 0; j < 8; j++) {
            float4 v = r4[j];
            acc[4*j+0] = fmaf(v.x, w, acc[4*j+0]);
            acc[4*j+1] = fmaf(v.y, w, acc[4*j+1]);
            acc[4*j+2] = fmaf(v.z, w, acc[4*j+2]);
            acc[4*j+3] = fmaf(v.w, w, acc[4*j+3]);
        }
    }
    {
        float bb = __ldg(&b4[t]);
        float fo = 0.f;
#pragma unroll
        for (int k = 0; k < KQ; k++) {
            float a = acc[k] + bb;
            float sg = 1.f / (1.f + expf(-a));
            fo = fmaf(sg, fp[k], fo);
        }
        f_out[(size_t)bs * HQ + t] = fo;
    }
}

// ---------------------------------------------------------------------------
extern "C" void kernel_launch(void* const* d_in, const int* in_sizes, int n_in,
                              void* d_out, int out_size)
{
    const float* xyz   = (const float*)d_in[0];
    const float* feats = (const float*)d_in[1];
    const float* W1 = (const float*)d_in[2];
    const float* b1 = (const float*)d_in[3];
    const float* W2 = (const float*)d_in[4];
    const float* b2 = (const float*)d_in[5];
    const float* W3 = (const float*)d_in[6];
    const float* b3 = (const float*)d_in[7];
    const float* W4 = (const float*)d_in[8];
    const float* b4 = (const float*)d_in[9];

    float* out     = (float*)d_out;
    float* new_xyz = out;                          // (B,S,3)
    float* f_out   = out + (size_t)BQ * SQ * 3;    // (B,S,H)

    const int smem_xyz = 3 * NQ * sizeof(float);   // 49152 = 48KB exactly

    fps_kernel <<<BQ, 1024>>>(xyz, new_xyz);
    ball_kernel<<<(BQ * SQ) / 128, 128, smem_xyz>>>(xyz, new_xyz);
    mlp_kernel <<<BQ * SQ, 128>>>(xyz, feats, new_xyz,
                                  W1, b1, W2, b2, W3, b3, W4, b4, f_out);
}

// round 3
// speedup vs baseline: 1.7046x; 1.7046x over previous
#include <cuda_runtime.h>
#include <math.h>

#define BQ 16
#define NQ 4096
#define SQ 1024
#define KQ 32
#define CQ 64
#define HQ 128
#define CAND_CAP 768

__device__ int g_group_idx[BQ * SQ * KQ];

// ---------------------------------------------------------------------------
// packed f32x2 helpers (Blackwell FFMA2 — 2x fp32 FMA throughput)
// ---------------------------------------------------------------------------
__device__ __forceinline__ unsigned long long fma2(
    unsigned long long a, unsigned long long b, unsigned long long c)
{
    unsigned long long d;
    asm("fma.rn.f32x2 %0, %1, %2, %3;" : "=l"(d) : "l"(a), "l"(b), "l"(c));
    return d;
}
__device__ __forceinline__ unsigned long long pack2(float w)
{
    unsigned long long d; unsigned u = __float_as_uint(w);
    asm("mov.b64 %0, {%1, %1};" : "=l"(d) : "r"(u));
    return d;
}
__device__ __forceinline__ float2 unpack2(unsigned long long a)
{
    float2 f;
    asm("mov.b64 {%0, %1}, %2;" : "=f"(f.x), "=f"(f.y) : "l"(a));
    return f;
}

// ---------------------------------------------------------------------------
// Kernel 1: FPS. One block/batch, 256 threads, 16 pts/thread in registers.
// redux.sync max on float bits + redux.sync min on index for exact
// first-index argmax tie-breaking.
// ---------------------------------------------------------------------------
__global__ __launch_bounds__(256) void fps_kernel(
    const float* __restrict__ xyz, float* __restrict__ new_xyz)
{
    const int b = blockIdx.x;
    const int t = threadIdx.x;
    const int lane = t & 31;
    const int warp = t >> 5;
    __shared__ unsigned sv[8];
    __shared__ int      si[8];
    __shared__ float    s_c[3];
    __shared__ int      s_idx;

    float px[16], py[16], pz[16], dmin[16];
    const float* xb = xyz + (size_t)b * NQ * 3;
#pragma unroll
    for (int r = 0; r < 16; r++) {
        int p = t + (r << 8);
        px[r] = xb[3 * p + 0];
        py[r] = xb[3 * p + 1];
        pz[r] = xb[3 * p + 2];
    }
    if (t == 0) {
        s_c[0] = px[0]; s_c[1] = py[0]; s_c[2] = pz[0];
        float* o = &new_xyz[(size_t)b * SQ * 3];
        o[0] = px[0]; o[1] = py[0]; o[2] = pz[0];
    }
    __syncthreads();
    float cx = s_c[0], cy = s_c[1], cz = s_c[2];
#pragma unroll
    for (int r = 0; r < 16; r++) dmin[r] = 3.0e38f;

    for (int i = 1; i < SQ; i++) {
        // fused: update dmin with previous center + local argmax (first idx)
        unsigned bv = 0; int bi = 0x7fffffff;
#pragma unroll
        for (int r = 0; r < 16; r++) {
            float dx = px[r] - cx, dy = py[r] - cy, dz = pz[r] - cz;
            float d = dx * dx;
            d = fmaf(dy, dy, d);
            d = fmaf(dz, dz, d);
            float dm = dmin[r];
            dm = d < dm ? d : dm;
            dmin[r] = dm;
            unsigned bits = __float_as_uint(dm);   // dm >= 0 -> order-preserving
            if (bits > bv) { bv = bits; bi = t + (r << 8); }
        }
        unsigned vmax = __reduce_max_sync(0xffffffffu, bv);
        int cnd = (bv == vmax) ? bi : 0x7fffffff;
        int imin = __reduce_min_sync(0xffffffffu, cnd);
        if (lane == 0) { sv[warp] = vmax; si[warp] = imin; }
        __syncthreads();
        if (t < 32) {
            unsigned vb = (t < 8) ? sv[t] : 0u;
            unsigned vm = __reduce_max_sync(0xffffffffu, vb);
            int c2 = (t < 8 && vb == vm) ? si[t] : 0x7fffffff;
            int im = __reduce_min_sync(0xffffffffu, c2);
            if (t == 0) s_idx = im;
        }
        __syncthreads();
        const int w = s_idx;
        if (t == (w & 255)) {
            const int r = w >> 8;
            s_c[0] = px[r]; s_c[1] = py[r]; s_c[2] = pz[r];
            float* o = &new_xyz[((size_t)b * SQ + i) * 3];
            o[0] = px[r]; o[1] = py[r]; o[2] = pz[r];
        }
        __syncthreads();
        cx = s_c[0]; cy = s_c[1]; cz = s_c[2];
    }
}

// ---------------------------------------------------------------------------
// Kernel 2: ball query, warp-per-center.
// Phase 1: ballot-compact in-ball candidates (key = dist_bits<<32 | idx).
// Phase 2: rank each candidate by pairwise compare; scatter rank<32.
// Fill (<32 candidates) with smallest out-of-ball indices == stable argsort.
// ---------------------------------------------------------------------------
__global__ __launch_bounds__(256) void ball_kernel(
    const float* __restrict__ xyz, const float* __restrict__ new_xyz)
{
    const int blk = blockIdx.x;
    const int b = blk >> 7;                 // 128 blocks per batch
    const int t = threadIdx.x;
    const int lane = t & 31;
    const int warp = t >> 5;                // 8 warps = 8 centers
    const int s = ((blk & 127) << 3) + warp;

    extern __shared__ float sm[];
    float* xs = sm;
    float* ys = sm + NQ;
    float* zs = sm + 2 * NQ;
    unsigned long long* cand =
        (unsigned long long*)(sm + 3 * NQ) + (size_t)warp * CAND_CAP;

    const float* xb = xyz + (size_t)b * NQ * 3;
    for (int idx = t; idx < NQ * 3; idx += 256) {
        float v = xb[idx];
        int p = idx / 3;
        int j = idx - 3 * p;
        if (j == 0) xs[p] = v; else if (j == 1) ys[p] = v; else zs[p] = v;
    }
    __syncthreads();

    const float* cc = &new_xyz[((size_t)b * SQ + s) * 3];
    const float cx = cc[0], cy = cc[1], cz = cc[2];

    // phase 1: compact candidates
    int cnt = 0;
#pragma unroll 4
    for (int j = 0; j < NQ / 32; j++) {
        int p = (j << 5) + lane;
        float dx = xs[p] - cx, dy = ys[p] - cy, dz = zs[p] - cz;
        float d = dx * dx;
        d = fmaf(dy, dy, d);
        d = fmaf(dz, dz, d);
        bool in = (d <= 0.04f);
        unsigned m = __ballot_sync(0xffffffffu, in);
        int pos = cnt + __popc(m & ((1u << lane) - 1u));
        if (in && pos < CAND_CAP)
            cand[pos] = ((unsigned long long)__float_as_uint(d) << 32) |
                        (unsigned)p;
        cnt += __popc(m);
    }
    __syncwarp();
    int L = cnt < CAND_CAP ? cnt : CAND_CAP;

    int* go = &g_group_idx[((size_t)b * SQ + s) * KQ];

    // phase 2: rank selection
    for (int c = lane; c < L; c += 32) {
        unsigned long long key = cand[c];
        int rank = 0;
        for (int j = 0; j < L; j++) rank += (cand[j] < key);
        if (rank < KQ) go[rank] = (int)(unsigned)key;
    }

    // fill if fewer than KQ in-ball (matches argsort of inf-keyed entries)
    if (L < KQ) {
        int fillpos = L;
        for (int base = 0; base < NQ && fillpos < KQ; base += 32) {
            int p = base + lane;
            float dx = xs[p] - cx, dy = ys[p] - cy, dz = zs[p] - cz;
            float d = dx * dx;
            d = fmaf(dy, dy, d);
            d = fmaf(dz, dz, d);
            bool ob = (d > 0.04f);
            unsigned m = __ballot_sync(0xffffffffu, ob);
            int pos = fillpos + __popc(m & ((1u << lane) - 1u));
            if (ob && pos < KQ) go[pos] = p;
            fillpos += __popc(m);
        }
    }
}

// ---------------------------------------------------------------------------
// Kernel 3: fused gather + 4-layer MLP + attention-weighted sum.
// One block per center, 128 threads = 1 output channel.
// Inner products use packed f32x2 FMA (2x fp32 throughput, identical rounding).
// ---------------------------------------------------------------------------
__global__ __launch_bounds__(128) void mlp_kernel(
    const float* __restrict__ xyz, const float* __restrict__ feats,
    const float* __restrict__ new_xyz,
    const float* __restrict__ W1, const float* __restrict__ b1,
    const float* __restrict__ W2, const float* __restrict__ b2,
    const float* __restrict__ W3, const float* __restrict__ b3,
    const float* __restrict__ W4, const float* __restrict__ b4,
    float* __restrict__ f_out)
{
    const int bs = blockIdx.x;
    const int b  = bs >> 10;
    const int t  = threadIdx.x;

    __shared__ __align__(16) float xn[3 * 36];
    __shared__ __align__(16) float bufA[128 * 36];
    __shared__ __align__(16) float bufB[128 * 36];
    __shared__ int   gi[KQ];
    __shared__ float ctr[3];

    if (t < KQ) gi[t] = g_group_idx[(size_t)bs * KQ + t];
    if (t >= KQ && t < KQ + 3) ctr[t - KQ] = new_xyz[(size_t)bs * 3 + (t - KQ)];
    __syncthreads();

    const float* fb = feats + (size_t)b * NQ * CQ;
    for (int e = t; e < KQ * CQ; e += 128) {
        int k = e >> 6, c = e & 63;
        bufA[c * 36 + k] = fb[(size_t)gi[k] * CQ + c];
    }
    if (t < 96) {
        int k = t & 31, j = t >> 5;
        xn[j * 36 + k] = xyz[((size_t)b * NQ + gi[k]) * 3 + j] - ctr[j];
    }
    __syncthreads();

    unsigned long long a2[16];

    // ----- Layer 1: 67 -> 128, relu -----
#pragma unroll
    for (int j = 0; j < 16; j++) a2[j] = 0ULL;
#pragma unroll
    for (int i = 0; i < 3; i++) {
        unsigned long long w2 = pack2(__ldg(&W1[i * HQ + t]));
        const ulonglong2* r2 = (const ulonglong2*)&xn[i * 36];
#pragma unroll
        for (int j = 0; j < 8; j++) {
            ulonglong2 v = r2[j];
            a2[2*j]   = fma2(v.x, w2, a2[2*j]);
            a2[2*j+1] = fma2(v.y, w2, a2[2*j+1]);
        }
    }
#pragma unroll 4
    for (int i = 0; i < CQ; i++) {
        unsigned long long w2 = pack2(__ldg(&W1[(3 + i) * HQ + t]));
        const ulonglong2* r2 = (const ulonglong2*)&bufA[i * 36];
#pragma unroll
        for (int j = 0; j < 8; j++) {
            ulonglong2 v = r2[j];
            a2[2*j]   = fma2(v.x, w2, a2[2*j]);
            a2[2*j+1] = fma2(v.y, w2, a2[2*j+1]);
        }
    }
    {
        float bb = __ldg(&b1[t]);
#pragma unroll
        for (int j = 0; j < 16; j++) {
            float2 f = unpack2(a2[j]);
            bufB[t * 36 + 2*j]     = fmaxf(f.x + bb, 0.f);
            bufB[t * 36 + 2*j + 1] = fmaxf(f.y + bb, 0.f);
        }
    }
    __syncthreads();

    // ----- Layer 2: 128 -> 128, relu -> f_prime in regs -----
#pragma unroll
    for (int j = 0; j < 16; j++) a2[j] = 0ULL;
#pragma unroll 4
    for (int i = 0; i < HQ; i++) {
        unsigned long long w2 = pack2(__ldg(&W2[i * HQ + t]));
        const ulonglong2* r2 = (const ulonglong2*)&bufB[i * 36];
#pragma unroll
        for (int j = 0; j < 8; j++) {
            ulonglong2 v = r2[j];
            a2[2*j]   = fma2(v.x, w2, a2[2*j]);
            a2[2*j+1] = fma2(v.y, w2, a2[2*j+1]);
        }
    }
    float fpk[KQ];
    float m = 0.f;
    {
        float bb = __ldg(&b2[t]);
#pragma unroll
        for (int j = 0; j < 16; j++) {
            float2 f = unpack2(a2[j]);
            float u = fmaxf(f.x + bb, 0.f);
            float v = fmaxf(f.y + bb, 0.f);
            fpk[2*j] = u; fpk[2*j+1] = v;
            m += u + v;
        }
        m *= (1.f / (float)KQ);
    }
#pragma unroll
    for (int k = 0; k < KQ; k++) bufA[t * 36 + k] = fpk[k] - m;
    __syncthreads();

    // ----- Layer 3: 131 -> 128, relu -----
#pragma unroll
    for (int j = 0; j < 16; j++) a2[j] = 0ULL;
#pragma unroll
    for (int i = 0; i < 3; i++) {
        unsigned long long w2 = pack2(__ldg(&W3[i * HQ + t]));
        const ulonglong2* r2 = (const ulonglong2*)&xn[i * 36];
#pragma unroll
        for (int j = 0; j < 8; j++) {
            ulonglong2 v = r2[j];
            a2[2*j]   = fma2(v.x, w2, a2[2*j]);
            a2[2*j+1] = fma2(v.y, w2, a2[2*j+1]);
        }
    }
#pragma unroll 4
    for (int i = 0; i < HQ; i++) {
        unsigned long long w2 = pack2(__ldg(&W3[(3 + i) * HQ + t]));
        const ulonglong2* r2 = (const ulonglong2*)&bufA[i * 36];
#pragma unroll
        for (int j = 0; j < 8; j++) {
            ulonglong2 v = r2[j];
            a2[2*j]   = fma2(v.x, w2, a2[2*j]);
            a2[2*j+1] = fma2(v.y, w2, a2[2*j+1]);
        }
    }
    {
        float bb = __ldg(&b3[t]);
#pragma unroll
        for (int j = 0; j < 16; j++) {
            float2 f = unpack2(a2[j]);
            bufB[t * 36 + 2*j]     = fmaxf(f.x + bb, 0.f);
            bufB[t * 36 + 2*j + 1] = fmaxf(f.y + bb, 0.f);
        }
    }
    __syncthreads();

    // ----- Layer 4: 128 -> 128, sigmoid; weighted sum -----
#pragma unroll
    for (int j = 0; j < 16; j++) a2[j] = 0ULL;
#pragma unroll 4
    for (int i = 0; i < HQ; i++) {
        unsigned long long w2 = pack2(__ldg(&W4[i * HQ + t]));
        const ulonglong2* r2 = (const ulonglong2*)&bufB[i * 36];
#pragma unroll
        for (int j = 0; j < 8; j++) {
            ulonglong2 v = r2[j];
            a2[2*j]   = fma2(v.x, w2, a2[2*j]);
            a2[2*j+1] = fma2(v.y, w2, a2[2*j+1]);
        }
    }
    {
        float bb = __ldg(&b4[t]);
        float fo = 0.f;
#pragma unroll
        for (int j = 0; j < 16; j++) {
            float2 f = unpack2(a2[j]);
            float s0 = 1.f / (1.f + expf(-(f.x + bb)));
            float s1 = 1.f / (1.f + expf(-(f.y + bb)));
            fo = fmaf(s0, fpk[2*j], fo);
            fo = fmaf(s1, fpk[2*j+1], fo);
        }
        f_out[(size_t)bs * HQ + t] = fo;
    }
}

// ---------------------------------------------------------------------------
extern "C" void kernel_launch(void* const* d_in, const int* in_sizes, int n_in,
                              void* d_out, int out_size)
{
    const float* xyz   = (const float*)d_in[0];
    const float* feats = (const float*)d_in[1];
    const float* W1 = (const float*)d_in[2];
    const float* b1 = (const float*)d_in[3];
    const float* W2 = (const float*)d_in[4];
    const float* b2 = (const float*)d_in[5];
    const float* W3 = (const float*)d_in[6];
    const float* b3 = (const float*)d_in[7];
    const float* W4 = (const float*)d_in[8];
    const float* b4 = (const float*)d_in[9];

    float* out     = (float*)d_out;
    float* new_xyz = out;
    float* f_out   = out + (size_t)BQ * SQ * 3;

    const int ball_smem = 3 * NQ * sizeof(float)
                        + 8 * CAND_CAP * sizeof(unsigned long long); // 96KB
    cudaFuncSetAttribute(ball_kernel,
                         cudaFuncAttributeMaxDynamicSharedMemorySize, ball_smem);

    fps_kernel <<<BQ, 256>>>(xyz, new_xyz);
    ball_kernel<<<(BQ * SQ) / 8, 256, ball_smem>>>(xyz, new_xyz);
    mlp_kernel <<<BQ * SQ, 128>>>(xyz, feats, new_xyz,
                                  W1, b1, W2, b2, W3, b3, W4, b4, f_out);
}

// round 4
// speedup vs baseline: 3.2013x; 1.8780x over previous
#include <cuda_runtime.h>
#include <math.h>

#define BQ 16
#define NQ 4096
#define SQ 1024
#define KQ 32
#define CQ 64
#define HQ 128
#define CAND_CAP 768
#define AS 140        // A-tile smem stride (conflict-free for frag loads)
#define FS 132        // F-tile smem stride

__device__ int g_group_idx[BQ * SQ * KQ];

// tf32-converted, zero-padded weights (padded K to multiple of 8)
__device__ unsigned g_W1[72 * 128];
__device__ unsigned g_W2[128 * 128];
__device__ unsigned g_W3[136 * 128];
__device__ unsigned g_W4[128 * 128];

__device__ __forceinline__ unsigned f2tf(float f) {
    unsigned r; asm("cvt.rna.tf32.f32 %0, %1;" : "=r"(r) : "f"(f)); return r;
}
__device__ __forceinline__ void mma_tf32(
    float& d0, float& d1, float& d2, float& d3,
    unsigned a0, unsigned a1, unsigned a2, unsigned a3,
    unsigned b0, unsigned b1)
{
    asm("mma.sync.aligned.m16n8k8.row.col.f32.tf32.tf32.f32 "
        "{%0,%1,%2,%3}, {%4,%5,%6,%7}, {%8,%9}, {%0,%1,%2,%3};"
        : "+f"(d0), "+f"(d1), "+f"(d2), "+f"(d3)
        : "r"(a0), "r"(a1), "r"(a2), "r"(a3), "r"(b0), "r"(b1));
}

// ---------------------------------------------------------------------------
// Kernel 0: convert + pad weights to tf32 once per launch.
// ---------------------------------------------------------------------------
__global__ void cvt_w_kernel(const float* __restrict__ W1,
                             const float* __restrict__ W2,
                             const float* __restrict__ W3,
                             const float* __restrict__ W4)
{
    int i = blockIdx.x * 256 + threadIdx.x;
    if (i < 72 * 128)  g_W1[i] = (i < 67 * 128)  ? f2tf(W1[i]) : 0u;
    if (i < 128 * 128) g_W2[i] = f2tf(W2[i]);
    if (i < 136 * 128) g_W3[i] = (i < 131 * 128) ? f2tf(W3[i]) : 0u;
    if (i < 128 * 128) g_W4[i] = f2tf(W4[i]);
}

// ---------------------------------------------------------------------------
// Kernel 1: FPS. One block/batch, 512 threads, 8 pts/thread, coords in smem.
// 2 barriers/iter; redux.sync argmax with exact first-index tie-breaking.
// ---------------------------------------------------------------------------
__global__ __launch_bounds__(512) void fps_kernel(
    const float* __restrict__ xyz, float* __restrict__ new_xyz)
{
    const int b = blockIdx.x;
    const int t = threadIdx.x;
    const int lane = t & 31;
    const int warp = t >> 5;
    extern __shared__ float sm[];
    float* xs = sm;
    float* ys = sm + NQ;
    float* zs = sm + 2 * NQ;
    __shared__ unsigned sv[16];
    __shared__ int      si[16];
    __shared__ int      s_idx;

    const float* xb = xyz + (size_t)b * NQ * 3;
    for (int idx = t; idx < NQ * 3; idx += 512) {
        float v = xb[idx];
        int p = idx / 3;
        int j = idx - 3 * p;
        if (j == 0) xs[p] = v; else if (j == 1) ys[p] = v; else zs[p] = v;
    }
    __syncthreads();

    float px[8], py[8], pz[8], dmin[8];
#pragma unroll
    for (int r = 0; r < 8; r++) {
        int p = t + (r << 9);
        px[r] = xs[p]; py[r] = ys[p]; pz[r] = zs[p];
        dmin[r] = 3.0e38f;
    }
    float cx = xs[0], cy = ys[0], cz = zs[0];
    if (t == 0) {
        float* o = &new_xyz[(size_t)b * SQ * 3];
        o[0] = cx; o[1] = cy; o[2] = cz;
    }

    for (int i = 1; i < SQ; i++) {
        unsigned bv = 0; int bi = 0x7fffffff;
#pragma unroll
        for (int r = 0; r < 8; r++) {
            float dx = px[r] - cx, dy = py[r] - cy, dz = pz[r] - cz;
            float d = dx * dx;
            d = fmaf(dy, dy, d);
            d = fmaf(dz, dz, d);
            float dm = dmin[r];
            dm = d < dm ? d : dm;
            dmin[r] = dm;
            unsigned bits = __float_as_uint(dm);
            if (bits > bv) { bv = bits; bi = t + (r << 9); }
        }
        unsigned vmax = __reduce_max_sync(0xffffffffu, bv);
        int cnd = (bv == vmax) ? bi : 0x7fffffff;
        int imin = __reduce_min_sync(0xffffffffu, cnd);
        if (lane == 0) { sv[warp] = vmax; si[warp] = imin; }
        __syncthreads();
        if (t < 32) {
            unsigned vb = (t < 16) ? sv[t] : 0u;
            unsigned vm = __reduce_max_sync(0xffffffffu, vb);
            int c2 = (t < 16 && vb == vm) ? si[t] : 0x7fffffff;
            int im = __reduce_min_sync(0xffffffffu, c2);
            if (t == 0) s_idx = im;
        }
        __syncthreads();
        const int w = s_idx;
        cx = xs[w]; cy = ys[w]; cz = zs[w];
        if (t == 0) {
            float* o = &new_xyz[((size_t)b * SQ + i) * 3];
            o[0] = cx; o[1] = cy; o[2] = cz;
        }
    }
}

// ---------------------------------------------------------------------------
// Kernel 2: ball query, warp-per-center (unchanged from R3 — passing).
// ---------------------------------------------------------------------------
__global__ __launch_bounds__(256) void ball_kernel(
    const float* __restrict__ xyz, const float* __restrict__ new_xyz)
{
    const int blk = blockIdx.x;
    const int b = blk >> 7;
    const int t = threadIdx.x;
    const int lane = t & 31;
    const int warp = t >> 5;
    const int s = ((blk & 127) << 3) + warp;

    extern __shared__ float sm[];
    float* xs = sm;
    float* ys = sm + NQ;
    float* zs = sm + 2 * NQ;
    unsigned long long* cand =
        (unsigned long long*)(sm + 3 * NQ) + (size_t)warp * CAND_CAP;

    const float* xb = xyz + (size_t)b * NQ * 3;
    for (int idx = t; idx < NQ * 3; idx += 256) {
        float v = xb[idx];
        int p = idx / 3;
        int j = idx - 3 * p;
        if (j == 0) xs[p] = v; else if (j == 1) ys[p] = v; else zs[p] = v;
    }
    __syncthreads();

    const float* cc = &new_xyz[((size_t)b * SQ + s) * 3];
    const float cx = cc[0], cy = cc[1], cz = cc[2];

    int cnt = 0;
#pragma unroll 4
    for (int j = 0; j < NQ / 32; j++) {
        int p = (j << 5) + lane;
        float dx = xs[p] - cx, dy = ys[p] - cy, dz = zs[p] - cz;
        float d = dx * dx;
        d = fmaf(dy, dy, d);
        d = fmaf(dz, dz, d);
        bool in = (d <= 0.04f);
        unsigned m = __ballot_sync(0xffffffffu, in);
        int pos = cnt + __popc(m & ((1u << lane) - 1u));
        if (in && pos < CAND_CAP)
            cand[pos] = ((unsigned long long)__float_as_uint(d) << 32) |
                        (unsigned)p;
        cnt += __popc(m);
    }
    __syncwarp();
    int L = cnt < CAND_CAP ? cnt : CAND_CAP;

    int* go = &g_group_idx[((size_t)b * SQ + s) * KQ];

    for (int c = lane; c < L; c += 32) {
        unsigned long long key = cand[c];
        int rank = 0;
        for (int j = 0; j < L; j++) rank += (cand[j] < key);
        if (rank < KQ) go[rank] = (int)(unsigned)key;
    }

    if (L < KQ) {
        int fillpos = L;
        for (int base = 0; base < NQ && fillpos < KQ; base += 32) {
            int p = base + lane;
            float dx = xs[p] - cx, dy = ys[p] - cy, dz = zs[p] - cz;
            float d = dx * dx;
            d = fmaf(dy, dy, d);
            d = fmaf(dz, dz, d);
            bool ob = (d > 0.04f);
            unsigned m = __ballot_sync(0xffffffffu, ob);
            int pos = fillpos + __popc(m & ((1u << lane) - 1u));
            if (ob && pos < KQ) go[pos] = p;
            fillpos += __popc(m);
        }
    }
}

// ---------------------------------------------------------------------------
// Kernel 3: fused MLP on tensor cores (tf32 mma.sync m16n8k8).
// Block = 1 center, 4 warps; warp handles a 32-wide channel slice.
// Rows = 32 neighbors (2 m-tiles), cols = 128 channels.
// ---------------------------------------------------------------------------
template<int KT>
__device__ __forceinline__ void gemm_layer(
    const unsigned* __restrict__ A, const unsigned* __restrict__ Wp,
    int g, int tg, int nb, float acc[2][4][4])
{
#pragma unroll
    for (int mi = 0; mi < 2; mi++)
#pragma unroll
        for (int nt = 0; nt < 4; nt++)
#pragma unroll
            for (int q = 0; q < 4; q++) acc[mi][nt][q] = 0.f;

#pragma unroll
    for (int kt = 0; kt < KT; kt++) {
        const int k0 = kt << 3;
        unsigned a[2][4];
#pragma unroll
        for (int mi = 0; mi < 2; mi++) {
            const unsigned* ab = A + (mi * 16 + g) * AS + k0 + tg;
            a[mi][0] = ab[0];
            a[mi][1] = ab[8 * AS];
            a[mi][2] = ab[4];
            a[mi][3] = ab[8 * AS + 4];
        }
#pragma unroll
        for (int nt = 0; nt < 4; nt++) {
            int nc = nb + (nt << 3) + g;
            unsigned b0 = __ldg(&Wp[(k0 + tg) * 128 + nc]);
            unsigned b1 = __ldg(&Wp[(k0 + 4 + tg) * 128 + nc]);
            mma_tf32(acc[0][nt][0], acc[0][nt][1], acc[0][nt][2], acc[0][nt][3],
                     a[0][0], a[0][1], a[0][2], a[0][3], b0, b1);
            mma_tf32(acc[1][nt][0], acc[1][nt][1], acc[1][nt][2], acc[1][nt][3],
                     a[1][0], a[1][1], a[1][2], a[1][3], b0, b1);
        }
    }
}

__global__ __launch_bounds__(128) void mlp_kernel(
    const float* __restrict__ xyz, const float* __restrict__ feats,
    const float* __restrict__ new_xyz,
    const float* __restrict__ b1, const float* __restrict__ b2,
    const float* __restrict__ b3, const float* __restrict__ b4,
    float* __restrict__ f_out)
{
    const int bs = blockIdx.x;
    const int b  = bs >> 10;
    const int t  = threadIdx.x;
    const int lane = t & 31;
    const int warp = t >> 5;
    const int g  = lane >> 2;
    const int tg = lane & 3;
    const int nb = warp << 5;

    __shared__ unsigned Abuf[32 * AS];   // tf32 activations (K-rows x channels)
    __shared__ float    Fbuf[32 * FS];   // f_prime fp32
    __shared__ float    xns[96];         // xn fp32 [3][32]
    __shared__ int      gi[KQ];
    __shared__ float    ctr[3];

    if (t < KQ) gi[t] = g_group_idx[(size_t)bs * KQ + t];
    if (t >= KQ && t < KQ + 3) ctr[t - KQ] = new_xyz[(size_t)bs * 3 + (t - KQ)];
    __syncthreads();

    // gather: A1 = [xn(3) | feats(64) | 0(5)] as tf32
    const float* fb = feats + (size_t)b * NQ * CQ;
    for (int e = t; e < KQ * CQ; e += 128) {
        int k = e >> 6, c = e & 63;
        Abuf[k * AS + 3 + c] = f2tf(fb[(size_t)gi[k] * CQ + c]);
    }
    if (t < 96) {
        int k = t & 31, j = t >> 5;
        float v = xyz[((size_t)b * NQ + gi[k]) * 3 + j] - ctr[j];
        xns[j * 32 + k] = v;
        Abuf[k * AS + j] = f2tf(v);
    }
    if (t < 32) {
#pragma unroll
        for (int c = 67; c < 72; c++) Abuf[t * AS + c] = 0u;
    }
    __syncthreads();

    float acc[2][4][4];

    // ----- Layer 1: 72(pad) -> 128, relu -----
    gemm_layer<9>(Abuf, g_W1, g, tg, nb, acc);
    __syncthreads();
#pragma unroll
    for (int nt = 0; nt < 4; nt++) {
        int cc = nb + (nt << 3) + 2 * tg;
        float bb0 = __ldg(&b1[cc]), bb1 = __ldg(&b1[cc + 1]);
#pragma unroll
        for (int mi = 0; mi < 2; mi++) {
            int r0 = mi * 16 + g;
            Abuf[r0 * AS + cc]           = f2tf(fmaxf(acc[mi][nt][0] + bb0, 0.f));
            Abuf[r0 * AS + cc + 1]       = f2tf(fmaxf(acc[mi][nt][1] + bb1, 0.f));
            Abuf[(r0 + 8) * AS + cc]     = f2tf(fmaxf(acc[mi][nt][2] + bb0, 0.f));
            Abuf[(r0 + 8) * AS + cc + 1] = f2tf(fmaxf(acc[mi][nt][3] + bb1, 0.f));
        }
    }
    __syncthreads();

    // ----- Layer 2: 128 -> 128, relu -> Fbuf (fp32) -----
    gemm_layer<16>(Abuf, g_W2, g, tg, nb, acc);
#pragma unroll
    for (int nt = 0; nt < 4; nt++) {
        int cc = nb + (nt << 3) + 2 * tg;
        float bb0 = __ldg(&b2[cc]), bb1 = __ldg(&b2[cc + 1]);
#pragma unroll
        for (int mi = 0; mi < 2; mi++) {
            int r0 = mi * 16 + g;
            Fbuf[r0 * FS + cc]           = fmaxf(acc[mi][nt][0] + bb0, 0.f);
            Fbuf[r0 * FS + cc + 1]       = fmaxf(acc[mi][nt][1] + bb1, 0.f);
            Fbuf[(r0 + 8) * FS + cc]     = fmaxf(acc[mi][nt][2] + bb0, 0.f);
            Fbuf[(r0 + 8) * FS + cc + 1] = fmaxf(acc[mi][nt][3] + bb1, 0.f);
        }
    }
    __syncthreads();   // all L2 mma + Fbuf stores done

    // A2 = [xn(3) | f'-mean(128) | 0(5)]
    {
        float m = 0.f;
#pragma unroll 8
        for (int k = 0; k < KQ; k++) m += Fbuf[k * FS + t];
        m *= (1.f / (float)KQ);
#pragma unroll 8
        for (int k = 0; k < KQ; k++)
            Abuf[k * AS + 3 + t] = f2tf(Fbuf[k * FS + t] - m);
    }
    if (t < 96) {
        int k = t & 31, j = t >> 5;
        Abuf[k * AS + j] = f2tf(xns[j * 32 + k]);
    }
    if (t < 32) {
#pragma unroll
        for (int c = 131; c < 136; c++) Abuf[t * AS + c] = 0u;
    }
    __syncthreads();

    // ----- Layer 3: 136(pad) -> 128, relu -----
    gemm_layer<17>(Abuf, g_W3, g, tg, nb, acc);
    __syncthreads();
#pragma unroll
    for (int nt = 0; nt < 4; nt++) {
        int cc = nb + (nt << 3) + 2 * tg;
        float bb0 = __ldg(&b3[cc]), bb1 = __ldg(&b3[cc + 1]);
#pragma unroll
        for (int mi = 0; mi < 2; mi++) {
            int r0 = mi * 16 + g;
            Abuf[r0 * AS + cc]           = f2tf(fmaxf(acc[mi][nt][0] + bb0, 0.f));
            Abuf[r0 * AS + cc + 1]       = f2tf(fmaxf(acc[mi][nt][1] + bb1, 0.f));
            Abuf[(r0 + 8) * AS + cc]     = f2tf(fmaxf(acc[mi][nt][2] + bb0, 0.f));
            Abuf[(r0 + 8) * AS + cc + 1] = f2tf(fmaxf(acc[mi][nt][3] + bb1, 0.f));
        }
    }
    __syncthreads();

    // ----- Layer 4: 128 -> 128, sigmoid; weighted sum over neighbors -----
    gemm_layer<16>(Abuf, g_W4, g, tg, nb, acc);
#pragma unroll
    for (int nt = 0; nt < 4; nt++) {
        int cc = nb + (nt << 3) + 2 * tg;
        float bb0 = __ldg(&b4[cc]), bb1 = __ldg(&b4[cc + 1]);
        float s0 = 0.f, s1 = 0.f;
#pragma unroll
        for (int mi = 0; mi < 2; mi++) {
            int r0 = mi * 16 + g;
            float a0 = 1.f / (1.f + __expf(-(acc[mi][nt][0] + bb0)));
            float a1 = 1.f / (1.f + __expf(-(acc[mi][nt][1] + bb1)));
            float a2 = 1.f / (1.f + __expf(-(acc[mi][nt][2] + bb0)));
            float a3 = 1.f / (1.f + __expf(-(acc[mi][nt][3] + bb1)));
            s0 = fmaf(a0, Fbuf[r0 * FS + cc], s0);
            s1 = fmaf(a1, Fbuf[r0 * FS + cc + 1], s1);
            s0 = fmaf(a2, Fbuf[(r0 + 8) * FS + cc], s0);
            s1 = fmaf(a3, Fbuf[(r0 + 8) * FS + cc + 1], s1);
        }
#pragma unroll
        for (int off = 4; off < 32; off <<= 1) {
            s0 += __shfl_xor_sync(0xffffffffu, s0, off);
            s1 += __shfl_xor_sync(0xffffffffu, s1, off);
        }
        if (g == 0) {
            f_out[(size_t)bs * HQ + cc]     = s0;
            f_out[(size_t)bs * HQ + cc + 1] = s1;
        }
    }
}

// ---------------------------------------------------------------------------
extern "C" void kernel_launch(void* const* d_in, const int* in_sizes, int n_in,
                              void* d_out, int out_size)
{
    const float* xyz   = (const float*)d_in[0];
    const float* feats = (const float*)d_in[1];
    const float* W1 = (const float*)d_in[2];
    const float* b1 = (const float*)d_in[3];
    const float* W2 = (const float*)d_in[4];
    const float* b2 = (const float*)d_in[5];
    const float* W3 = (const float*)d_in[6];
    const float* b3 = (const float*)d_in[7];
    const float* W4 = (const float*)d_in[8];
    const float* b4 = (const float*)d_in[9];

    float* out     = (float*)d_out;
    float* new_xyz = out;
    float* f_out   = out + (size_t)BQ * SQ * 3;

    const int fps_smem  = 3 * NQ * sizeof(float);                       // 48KB
    const int ball_smem = fps_smem + 8 * CAND_CAP * sizeof(long long);  // 96KB
    cudaFuncSetAttribute(fps_kernel,
                         cudaFuncAttributeMaxDynamicSharedMemorySize, fps_smem);
    cudaFuncSetAttribute(ball_kernel,
                         cudaFuncAttributeMaxDynamicSharedMemorySize, ball_smem);

    cvt_w_kernel<<<(136 * 128 + 255) / 256, 256>>>(W1, W2, W3, W4);
    fps_kernel <<<BQ, 512, fps_smem>>>(xyz, new_xyz);
    ball_kernel<<<(BQ * SQ) / 8, 256, ball_smem>>>(xyz, new_xyz);
    mlp_kernel <<<BQ * SQ, 128>>>(xyz, feats, new_xyz,
                                  b1, b2, b3, b4, f_out);
}

// round 5
// speedup vs baseline: 3.7404x; 1.1684x over previous
#include <cuda_runtime.h>
#include <math.h>

#define BQ 16
#define NQ 4096
#define SQ 1024
#define KQ 32
#define CQ 64
#define HQ 128
#define CAND_CAP 768
#define AS 140        // A-tile smem stride (words)
#define FS 132        // F-tile smem stride (words)

__device__ int g_group_idx[BQ * SQ * KQ];

// tf32-converted, zero-padded weights (K padded to multiple of 8)
__device__ unsigned g_W1[72 * 128];
__device__ unsigned g_W2[128 * 128];
__device__ unsigned g_W3[136 * 128];
__device__ unsigned g_W4[128 * 128];

__device__ __forceinline__ unsigned f2tf(float f) {
    unsigned r; asm("cvt.rna.tf32.f32 %0, %1;" : "=r"(r) : "f"(f)); return r;
}
__device__ __forceinline__ void mma_tf32(
    float& d0, float& d1, float& d2, float& d3,
    unsigned a0, unsigned a1, unsigned a2, unsigned a3,
    unsigned b0, unsigned b1)
{
    asm("mma.sync.aligned.m16n8k8.row.col.f32.tf32.tf32.f32 "
        "{%0,%1,%2,%3}, {%4,%5,%6,%7}, {%8,%9}, {%0,%1,%2,%3};"
        : "+f"(d0), "+f"(d1), "+f"(d2), "+f"(d3)
        : "r"(a0), "r"(a1), "r"(a2), "r"(a3), "r"(b0), "r"(b1));
}

// ---------------------------------------------------------------------------
// Kernel 0: convert + pad weights to tf32 once per launch.
// ---------------------------------------------------------------------------
__global__ void cvt_w_kernel(const float* __restrict__ W1,
                             const float* __restrict__ W2,
                             const float* __restrict__ W3,
                             const float* __restrict__ W4)
{
    int i = blockIdx.x * 256 + threadIdx.x;
    if (i < 72 * 128)  g_W1[i] = (i < 67 * 128)  ? f2tf(W1[i]) : 0u;
    if (i < 128 * 128) g_W2[i] = f2tf(W2[i]);
    if (i < 136 * 128) g_W3[i] = (i < 131 * 128) ? f2tf(W3[i]) : 0u;
    if (i < 128 * 128) g_W4[i] = f2tf(W4[i]);
}

// ---------------------------------------------------------------------------
// Kernel 1: FPS. One block/batch, 512 threads, 8 pts/thread, coords in smem.
// ONE barrier/iter: parity-double-buffered warp partials; every warp
// redundantly computes the block argmax via redux.sync.
// ---------------------------------------------------------------------------
__global__ __launch_bounds__(512) void fps_kernel(
    const float* __restrict__ xyz, float* __restrict__ new_xyz)
{
    const int b = blockIdx.x;
    const int t = threadIdx.x;
    const int lane = t & 31;
    const int warp = t >> 5;
    extern __shared__ float sm[];
    float* xs = sm;
    float* ys = sm + NQ;
    float* zs = sm + 2 * NQ;
    __shared__ unsigned sv[2][16];
    __shared__ int      si[2][16];

    const float* xb = xyz + (size_t)b * NQ * 3;
    for (int idx = t; idx < NQ * 3; idx += 512) {
        float v = xb[idx];
        int p = idx / 3;
        int j = idx - 3 * p;
        if (j == 0) xs[p] = v; else if (j == 1) ys[p] = v; else zs[p] = v;
    }
    __syncthreads();

    float px[8], py[8], pz[8], dmin[8];
#pragma unroll
    for (int r = 0; r < 8; r++) {
        int p = t + (r << 9);
        px[r] = xs[p]; py[r] = ys[p]; pz[r] = zs[p];
        dmin[r] = 3.0e38f;
    }
    float cx = xs[0], cy = ys[0], cz = zs[0];
    if (t == 0) {
        float* o = &new_xyz[(size_t)b * SQ * 3];
        o[0] = cx; o[1] = cy; o[2] = cz;
    }

    for (int i = 1; i < SQ; i++) {
        unsigned bv = 0; int bi = 0x7fffffff;
#pragma unroll
        for (int r = 0; r < 8; r++) {
            float dx = px[r] - cx, dy = py[r] - cy, dz = pz[r] - cz;
            float d = dx * dx;
            d = fmaf(dy, dy, d);
            d = fmaf(dz, dz, d);
            float dm = dmin[r];
            dm = d < dm ? d : dm;
            dmin[r] = dm;
            unsigned bits = __float_as_uint(dm);
            if (bits > bv) { bv = bits; bi = t + (r << 9); }
        }
        unsigned vmax = __reduce_max_sync(0xffffffffu, bv);
        int cnd = (bv == vmax) ? bi : 0x7fffffff;
        int imin = __reduce_min_sync(0xffffffffu, cnd);
        const int buf = i & 1;
        if (lane == 0) { sv[buf][warp] = vmax; si[buf][warp] = imin; }
        __syncthreads();
        // every warp reduces the 16 partials (lanes 16-31 read duplicates)
        unsigned vb = sv[buf][lane & 15];
        int      ib = si[buf][lane & 15];
        unsigned vm = __reduce_max_sync(0xffffffffu, vb);
        int c2 = (vb == vm) ? ib : 0x7fffffff;
        int im = __reduce_min_sync(0xffffffffu, c2);
        cx = xs[im]; cy = ys[im]; cz = zs[im];
        if (t == 0) {
            float* o = &new_xyz[((size_t)b * SQ + i) * 3];
            o[0] = cx; o[1] = cy; o[2] = cz;
        }
    }
}

// ---------------------------------------------------------------------------
// Kernel 2: ball query, warp-per-center (unchanged — passing).
// ---------------------------------------------------------------------------
__global__ __launch_bounds__(256) void ball_kernel(
    const float* __restrict__ xyz, const float* __restrict__ new_xyz)
{
    const int blk = blockIdx.x;
    const int b = blk >> 7;
    const int t = threadIdx.x;
    const int lane = t & 31;
    const int warp = t >> 5;
    const int s = ((blk & 127) << 3) + warp;

    extern __shared__ float sm[];
    float* xs = sm;
    float* ys = sm + NQ;
    float* zs = sm + 2 * NQ;
    unsigned long long* cand =
        (unsigned long long*)(sm + 3 * NQ) + (size_t)warp * CAND_CAP;

    const float* xb = xyz + (size_t)b * NQ * 3;
    for (int idx = t; idx < NQ * 3; idx += 256) {
        float v = xb[idx];
        int p = idx / 3;
        int j = idx - 3 * p;
        if (j == 0) xs[p] = v; else if (j == 1) ys[p] = v; else zs[p] = v;
    }
    __syncthreads();

    const float* cc = &new_xyz[((size_t)b * SQ + s) * 3];
    const float cx = cc[0], cy = cc[1], cz = cc[2];

    int cnt = 0;
#pragma unroll 4
    for (int j = 0; j < NQ / 32; j++) {
        int p = (j << 5) + lane;
        float dx = xs[p] - cx, dy = ys[p] - cy, dz = zs[p] - cz;
        float d = dx * dx;
        d = fmaf(dy, dy, d);
        d = fmaf(dz, dz, d);
        bool in = (d <= 0.04f);
        unsigned m = __ballot_sync(0xffffffffu, in);
        int pos = cnt + __popc(m & ((1u << lane) - 1u));
        if (in && pos < CAND_CAP)
            cand[pos] = ((unsigned long long)__float_as_uint(d) << 32) |
                        (unsigned)p;
        cnt += __popc(m);
    }
    __syncwarp();
    int L = cnt < CAND_CAP ? cnt : CAND_CAP;

    int* go = &g_group_idx[((size_t)b * SQ + s) * KQ];

    for (int c = lane; c < L; c += 32) {
        unsigned long long key = cand[c];
        int rank = 0;
        for (int j = 0; j < L; j++) rank += (cand[j] < key);
        if (rank < KQ) go[rank] = (int)(unsigned)key;
    }

    if (L < KQ) {
        int fillpos = L;
        for (int base = 0; base < NQ && fillpos < KQ; base += 32) {
            int p = base + lane;
            float dx = xs[p] - cx, dy = ys[p] - cy, dz = zs[p] - cz;
            float d = dx * dx;
            d = fmaf(dy, dy, d);
            d = fmaf(dz, dz, d);
            bool ob = (d > 0.04f);
            unsigned m = __ballot_sync(0xffffffffu, ob);
            int pos = fillpos + __popc(m & ((1u << lane) - 1u));
            if (ob && pos < KQ) go[pos] = p;
            fillpos += __popc(m);
        }
    }
}

// ---------------------------------------------------------------------------
// Kernel 3: fused MLP, tf32 mma.sync, TWO centers per block (M=64).
// 128 threads, 4 warps x 32 channels, 4 m-tiles -> B-fragment reuse 4x.
// ---------------------------------------------------------------------------
template<int KT>
__device__ __forceinline__ void gemm_layer(
    const unsigned* __restrict__ A, const unsigned* __restrict__ Wp,
    int g, int tg, int nb, float acc[4][4][4])
{
#pragma unroll
    for (int mi = 0; mi < 4; mi++)
#pragma unroll
        for (int nt = 0; nt < 4; nt++)
#pragma unroll
            for (int q = 0; q < 4; q++) acc[mi][nt][q] = 0.f;

#pragma unroll
    for (int kt = 0; kt < KT; kt++) {
        const int k0 = kt << 3;
        unsigned a[4][4];
#pragma unroll
        for (int mi = 0; mi < 4; mi++) {
            const unsigned* ab = A + (mi * 16 + g) * AS + k0 + tg;
            a[mi][0] = ab[0];
            a[mi][1] = ab[8 * AS];
            a[mi][2] = ab[4];
            a[mi][3] = ab[8 * AS + 4];
        }
#pragma unroll
        for (int nt = 0; nt < 4; nt++) {
            int nc = nb + (nt << 3) + g;
            unsigned b0 = __ldg(&Wp[(k0 + tg) * 128 + nc]);
            unsigned b1 = __ldg(&Wp[(k0 + 4 + tg) * 128 + nc]);
#pragma unroll
            for (int mi = 0; mi < 4; mi++)
                mma_tf32(acc[mi][nt][0], acc[mi][nt][1],
                         acc[mi][nt][2], acc[mi][nt][3],
                         a[mi][0], a[mi][1], a[mi][2], a[mi][3], b0, b1);
        }
    }
}

__global__ __launch_bounds__(128) void mlp_kernel(
    const float* __restrict__ xyz, const float* __restrict__ feats,
    const float* __restrict__ new_xyz,
    const float* __restrict__ b1, const float* __restrict__ b2,
    const float* __restrict__ b3, const float* __restrict__ b4,
    float* __restrict__ f_out)
{
    const int bs0 = blockIdx.x << 1;       // first of 2 centers
    const int b   = bs0 >> 10;
    const int t   = threadIdx.x;
    const int lane = t & 31;
    const int warp = t >> 5;
    const int g  = lane >> 2;
    const int tg = lane & 3;
    const int nb = warp << 5;

    extern __shared__ unsigned dynsm[];
    unsigned* Abuf = dynsm;                          // 64*AS tf32
    float*    Fbuf = (float*)(dynsm + 64 * AS);      // 64*FS fp32
    float*    xns  = Fbuf + 64 * FS;                 // 192 fp32
    __shared__ int   gi[2 * KQ];
    __shared__ float ctr[6];

    if (t < 2 * KQ) gi[t] = g_group_idx[(size_t)bs0 * KQ + t];
    if (t >= 64 && t < 70) ctr[t - 64] = new_xyz[(size_t)bs0 * 3 + (t - 64)];
    __syncthreads();

    // gather feats: rows 0-31 center0, 32-63 center1
    const float* fb = feats + (size_t)b * NQ * CQ;
    for (int e = t; e < 2 * KQ * CQ; e += 128) {
        int k = e >> 6, c = e & 63;
        Abuf[k * AS + 3 + c] = f2tf(fb[(size_t)gi[k] * CQ + c]);
    }
    // gather xyz, normalize
    for (int e = t; e < 192; e += 128) {
        int c = e / 96, r = e - c * 96;
        int j = r >> 5, k = r & 31;
        float v = xyz[((size_t)b * NQ + gi[c * KQ + k]) * 3 + j] - ctr[c * 3 + j];
        xns[e] = v;
        Abuf[(c * KQ + k) * AS + j] = f2tf(v);
    }
    if (t < 64) {
#pragma unroll
        for (int c = 67; c < 72; c++) Abuf[t * AS + c] = 0u;
    }
    __syncthreads();

    float acc[4][4][4];

    // ----- Layer 1: 72(pad) -> 128, relu -----
    gemm_layer<9>(Abuf, g_W1, g, tg, nb, acc);
    __syncthreads();
#pragma unroll
    for (int nt = 0; nt < 4; nt++) {
        int cc = nb + (nt << 3) + 2 * tg;
        float bb0 = __ldg(&b1[cc]), bb1 = __ldg(&b1[cc + 1]);
#pragma unroll
        for (int mi = 0; mi < 4; mi++) {
            int r0 = mi * 16 + g;
            Abuf[r0 * AS + cc]           = f2tf(fmaxf(acc[mi][nt][0] + bb0, 0.f));
            Abuf[r0 * AS + cc + 1]       = f2tf(fmaxf(acc[mi][nt][1] + bb1, 0.f));
            Abuf[(r0 + 8) * AS + cc]     = f2tf(fmaxf(acc[mi][nt][2] + bb0, 0.f));
            Abuf[(r0 + 8) * AS + cc + 1] = f2tf(fmaxf(acc[mi][nt][3] + bb1, 0.f));
        }
    }
    __syncthreads();

    // ----- Layer 2: 128 -> 128, relu -> Fbuf (fp32) -----
    gemm_layer<16>(Abuf, g_W2, g, tg, nb, acc);
#pragma unroll
    for (int nt = 0; nt < 4; nt++) {
        int cc = nb + (nt << 3) + 2 * tg;
        float bb0 = __ldg(&b2[cc]), bb1 = __ldg(&b2[cc + 1]);
#pragma unroll
        for (int mi = 0; mi < 4; mi++) {
            int r0 = mi * 16 + g;
            Fbuf[r0 * FS + cc]           = fmaxf(acc[mi][nt][0] + bb0, 0.f);
            Fbuf[r0 * FS + cc + 1]       = fmaxf(acc[mi][nt][1] + bb1, 0.f);
            Fbuf[(r0 + 8) * FS + cc]     = fmaxf(acc[mi][nt][2] + bb0, 0.f);
            Fbuf[(r0 + 8) * FS + cc + 1] = fmaxf(acc[mi][nt][3] + bb1, 0.f);
        }
    }
    __syncthreads();   // L2 gemm reads of Abuf done; Fbuf complete

    // A2 = [xn(3) | f'-mean(128) | 0(5)], per center
#pragma unroll
    for (int c = 0; c < 2; c++) {
        float m = 0.f;
#pragma unroll 8
        for (int k = 0; k < KQ; k++) m += Fbuf[(c * KQ + k) * FS + t];
        m *= (1.f / (float)KQ);
#pragma unroll 8
        for (int k = 0; k < KQ; k++)
            Abuf[(c * KQ + k) * AS + 3 + t] = f2tf(Fbuf[(c * KQ + k) * FS + t] - m);
    }
    for (int e = t; e < 192; e += 128) {
        int c = e / 96, r = e - c * 96;
        int j = r >> 5, k = r & 31;
        Abuf[(c * KQ + k) * AS + j] = f2tf(xns[e]);
    }
    if (t < 64) {
#pragma unroll
        for (int c = 131; c < 136; c++) Abuf[t * AS + c] = 0u;
    }
    __syncthreads();

    // ----- Layer 3: 136(pad) -> 128, relu -----
    gemm_layer<17>(Abuf, g_W3, g, tg, nb, acc);
    __syncthreads();
#pragma unroll
    for (int nt = 0; nt < 4; nt++) {
        int cc = nb + (nt << 3) + 2 * tg;
        float bb0 = __ldg(&b3[cc]), bb1 = __ldg(&b3[cc + 1]);
#pragma unroll
        for (int mi = 0; mi < 4; mi++) {
            int r0 = mi * 16 + g;
            Abuf[r0 * AS + cc]           = f2tf(fmaxf(acc[mi][nt][0] + bb0, 0.f));
            Abuf[r0 * AS + cc + 1]       = f2tf(fmaxf(acc[mi][nt][1] + bb1, 0.f));
            Abuf[(r0 + 8) * AS + cc]     = f2tf(fmaxf(acc[mi][nt][2] + bb0, 0.f));
            Abuf[(r0 + 8) * AS + cc + 1] = f2tf(fmaxf(acc[mi][nt][3] + bb1, 0.f));
        }
    }
    __syncthreads();

    // ----- Layer 4: 128 -> 128, sigmoid; weighted sum per center -----
    gemm_layer<16>(Abuf, g_W4, g, tg, nb, acc);
#pragma unroll
    for (int nt = 0; nt < 4; nt++) {
        int cc = nb + (nt << 3) + 2 * tg;
        float bb0 = __ldg(&b4[cc]), bb1 = __ldg(&b4[cc + 1]);
        float s0[2] = {0.f, 0.f}, s1[2] = {0.f, 0.f};
#pragma unroll
        for (int mi = 0; mi < 4; mi++) {
            int c = mi >> 1;
            int r0 = mi * 16 + g;
            float a0 = 1.f / (1.f + __expf(-(acc[mi][nt][0] + bb0)));
            float a1 = 1.f / (1.f + __expf(-(acc[mi][nt][1] + bb1)));
            float a2 = 1.f / (1.f + __expf(-(acc[mi][nt][2] + bb0)));
            float a3 = 1.f / (1.f + __expf(-(acc[mi][nt][3] + bb1)));
            s0[c] = fmaf(a0, Fbuf[r0 * FS + cc], s0[c]);
            s1[c] = fmaf(a1, Fbuf[r0 * FS + cc + 1], s1[c]);
            s0[c] = fmaf(a2, Fbuf[(r0 + 8) * FS + cc], s0[c]);
            s1[c] = fmaf(a3, Fbuf[(r0 + 8) * FS + cc + 1], s1[c]);
        }
#pragma unroll
        for (int off = 4; off < 32; off <<= 1) {
            s0[0] += __shfl_xor_sync(0xffffffffu, s0[0], off);
            s1[0] += __shfl_xor_sync(0xffffffffu, s1[0], off);
            s0[1] += __shfl_xor_sync(0xffffffffu, s0[1], off);
            s1[1] += __shfl_xor_sync(0xffffffffu, s1[1], off);
        }
        if (g == 0) {
            f_out[(size_t)bs0 * HQ + cc]           = s0[0];
            f_out[(size_t)bs0 * HQ + cc + 1]       = s1[0];
            f_out[((size_t)bs0 + 1) * HQ + cc]     = s0[1];
            f_out[((size_t)bs0 + 1) * HQ + cc + 1] = s1[1];
        }
    }
}

// ---------------------------------------------------------------------------
extern "C" void kernel_launch(void* const* d_in, const int* in_sizes, int n_in,
                              void* d_out, int out_size)
{
    const float* xyz   = (const float*)d_in[0];
    const float* feats = (const float*)d_in[1];
    const float* W1 = (const float*)d_in[2];
    const float* b1 = (const float*)d_in[3];
    const float* W2 = (const float*)d_in[4];
    const float* b2 = (const float*)d_in[5];
    const float* W3 = (const float*)d_in[6];
    const float* b3 = (const float*)d_in[7];
    const float* W4 = (const float*)d_in[8];
    const float* b4 = (const float*)d_in[9];

    float* out     = (float*)d_out;
    float* new_xyz = out;
    float* f_out   = out + (size_t)BQ * SQ * 3;

    const int fps_smem  = 3 * NQ * sizeof(float);                       // 48KB
    const int ball_smem = fps_smem + 8 * CAND_CAP * sizeof(long long);  // 96KB
    const int mlp_smem  = (64 * AS) * 4 + (64 * FS) * 4 + 192 * 4;      // ~70KB
    cudaFuncSetAttribute(fps_kernel,
                         cudaFuncAttributeMaxDynamicSharedMemorySize, fps_smem);
    cudaFuncSetAttribute(ball_kernel,
                         cudaFuncAttributeMaxDynamicSharedMemorySize, ball_smem);
    cudaFuncSetAttribute(mlp_kernel,
                         cudaFuncAttributeMaxDynamicSharedMemorySize, mlp_smem);

    cvt_w_kernel<<<(136 * 128 + 255) / 256, 256>>>(W1, W2, W3, W4);
    fps_kernel <<<BQ, 512, fps_smem>>>(xyz, new_xyz);
    ball_kernel<<<(BQ * SQ) / 8, 256, ball_smem>>>(xyz, new_xyz);
    mlp_kernel <<<(BQ * SQ) / 2, 128, mlp_smem>>>(xyz, feats, new_xyz,
                                                  b1, b2, b3, b4, f_out);
}